// round 10
// baseline (speedup 1.0000x reference)
#include <cuda_runtime.h>

typedef unsigned int u32;

#define BB 4
#define TT 2048
#define DD 1024
#define RR 32

#define BM 64
#define BN 32
#define DC 256
#define NT (TT / BN)

// scratch (no allocations allowed)
__device__ float g_y[BB * TT * RR];     // y = x @ U (tf32-rounded)
__device__ float g_n[BB * TT];          // ||y||^2
// pair-interleaved rounded x: [tile(256)][d(1024)][32 perm keys]
__device__ float g_xrp[BB * TT * DD];

__device__ __forceinline__ u32 s2u(const void* p) {
    u32 a;
    asm("{ .reg .u64 t; cvta.to.shared.u64 t, %1; cvt.u32.u64 %0, t; }" : "=r"(a) : "l"(p));
    return a;
}
__device__ __forceinline__ void cp16(u32 dst, const void* src) {
    asm volatile("cp.async.cg.shared.global [%0], [%1], 16;" :: "r"(dst), "l"(src));
}
__device__ __forceinline__ u32 fu(float v) { return __float_as_uint(v); }
__device__ __forceinline__ float tf32f(float v) {
    u32 r;
    asm("cvt.rna.tf32.f32 %0, %1;" : "=r"(r) : "f"(v));
    return __uint_as_float(r);
}

// ---------------------------------------------------------------------------
// Kernel 1: y = x @ U (rounded), n = rowsum(y*y), g_xrp = permuted round(x).
// Block: 256 threads / 8 warps, 64 rows (= 2 key tiles). Grid: 128.
// ---------------------------------------------------------------------------
#define K1_XSTR 132
#define K1_XF(q) ((q) * 8448)             // [64][132] floats
#define K1_UF(q) (16896 + (q) * 4608)     // [128][36] floats
#define K1_SMEM ((16896 + 2 * 4608) * 4)  // 104448 B

__global__ __launch_bounds__(256, 1) void yn_kernel(const float* __restrict__ x,
                                                    const float* __restrict__ U) {
    extern __shared__ float s[];
    const u32 su = s2u(s);

    const int tid  = threadIdx.x;
    const int w    = tid >> 5;
    const int lane = tid & 31;
    const int row0 = blockIdx.x * 64;

    // permuted slot for this lane's key-in-tile index o = lane:
    // slot(o) = (o%4)*8 + (o/8)*2 + (o%8)/4
    const int slot = (lane & 3) * 8 + (lane >> 3) * 2 + ((lane & 7) >> 2);

    for (int idx = tid; idx < 2048; idx += 256) {
        int r_ = idx >> 5, u = idx & 31;
        cp16(su + K1_XF(0) * 4 + (r_ * K1_XSTR + u * 4) * 4,
             x + (size_t)(row0 + r_) * DD + u * 4);
    }
    for (int idx = tid; idx < 1024; idx += 256) {
        int d = idx >> 3, u = idx & 7;
        cp16(su + K1_UF(0) * 4 + (d * 36 + u * 4) * 4,
             U + (size_t)d * RR + u * 4);
    }
    asm volatile("cp.async.commit_group;" ::: "memory");

    float acc[8];
#pragma unroll
    for (int k = 0; k < 8; k++) acc[k] = 0.f;

    for (int c = 0; c < 8; c++) {
        const int q = c & 1;
        asm volatile("cp.async.wait_group 0;" ::: "memory");
        __syncthreads();

        if (c + 1 < 8) {
            const int d0n = (c + 1) * 128;
            for (int idx = tid; idx < 2048; idx += 256) {
                int r_ = idx >> 5, u = idx & 31;
                cp16(su + K1_XF(1 - q) * 4 + (r_ * K1_XSTR + u * 4) * 4,
                     x + (size_t)(row0 + r_) * DD + d0n + u * 4);
            }
            for (int idx = tid; idx < 1024; idx += 256) {
                int d = idx >> 3, u = idx & 7;
                cp16(su + K1_UF(1 - q) * 4 + ((d * 36 + u * 4)) * 4,
                     U + (size_t)(d0n + d) * RR + u * 4);
            }
            asm volatile("cp.async.commit_group;" ::: "memory");
        }

        const float* sX = s + K1_XF(q);
        const float* sU = s + K1_UF(q);
#pragma unroll
        for (int dd4 = 0; dd4 < 32; dd4++) {
            float u0 = sU[(dd4 * 4 + 0) * 36 + lane];
            float u1 = sU[(dd4 * 4 + 1) * 36 + lane];
            float u2 = sU[(dd4 * 4 + 2) * 36 + lane];
            float u3 = sU[(dd4 * 4 + 3) * 36 + lane];
#pragma unroll
            for (int k = 0; k < 8; k++) {
                const float4 xv = *(const float4*)&sX[(w * 8 + k) * K1_XSTR + dd4 * 4];
                acc[k] = fmaf(xv.x, u0, acc[k]);
                acc[k] = fmaf(xv.y, u1, acc[k]);
                acc[k] = fmaf(xv.z, u2, acc[k]);
                acc[k] = fmaf(xv.w, u3, acc[k]);
            }
        }

        // scatter rounded chunk to g_xrp (pair-interleaved layout)
        const int d0 = c * 128;
        for (int item = w; item < 64; item += 8) {   // item = jt(2) x d4(32)
            const int jt = item >> 5, d4 = item & 31;
            const float4 xv = *(const float4*)&sX[(jt * 32 + lane) * K1_XSTR + d4 * 4];
            const size_t gt = (size_t)(blockIdx.x * 2 + jt) * 1024 + d0 + d4 * 4;
            g_xrp[(gt + 0) * 32 + slot] = tf32f(xv.x);
            g_xrp[(gt + 1) * 32 + slot] = tf32f(xv.y);
            g_xrp[(gt + 2) * 32 + slot] = tf32f(xv.z);
            g_xrp[(gt + 3) * 32 + slot] = tf32f(xv.w);
        }
    }

#pragma unroll
    for (int k = 0; k < 8; k++) {
        int rg = row0 + w * 8 + k;
        float ar = tf32f(acc[k]);
        g_y[(size_t)rg * RR + lane] = ar;
        float v = ar * ar;
#pragma unroll
        for (int off = 16; off; off >>= 1)
            v += __shfl_xor_sync(0xffffffffu, v, off);
        if (lane == 0) g_n[rg] = v;
    }
}

// ---------------------------------------------------------------------------
// Kernel 2: flash attention, mma.sync tf32 (R6 partition).
// 8 warps = 2 wm x 4 wn; warp tile 32m x 64n; 2 CTAs/SM.
// X and P in pair-interleaved layouts -> LDS.128 fragment loads.
// ---------------------------------------------------------------------------
#define YI_F 0                          // [64][36]
#define P_F  2304                       // [64][36]  pair-slot layout per row
#define YJ_F(q) (4608 + (q) * 1152)     // [32][36] x2
#define NJ_F(q) (6912 + (q) * 32)       // [32] x2
#define L_F  0                          // [4][64] (reuses YI in epilogue)
#define X_F(q) (6976 + (q) * 9216)      // [256 d][36] x2
#define SMEM_TOTAL ((6976 + 2 * 9216) * 4)   // 101632 B

#define YSTR 36

__device__ __forceinline__ void mma8(float* d, const u32* a, u32 b0, u32 b1,
                                     const float* c) {
    asm volatile(
        "mma.sync.aligned.m16n8k8.row.col.f32.tf32.tf32.f32 "
        "{%0,%1,%2,%3}, {%4,%5,%6,%7}, {%8,%9}, {%10,%11,%12,%13};"
        : "=f"(d[0]), "=f"(d[1]), "=f"(d[2]), "=f"(d[3])
        : "r"(a[0]), "r"(a[1]), "r"(a[2]), "r"(a[3]), "r"(b0), "r"(b1),
          "f"(c[0]), "f"(c[1]), "f"(c[2]), "f"(c[3]));
}

__global__ __launch_bounds__(256, 2) void flash_kernel(float* __restrict__ out) {
    extern __shared__ float s[];
    const u32 su = s2u(s);

    const int tid  = threadIdx.x;
    const int w    = tid >> 5;
    const int lane = tid & 31;
    const int wm   = w >> 2;        // 0..1 : 32 query rows each
    const int wn   = w & 3;         // 0..3 : 8 s-cols (MMA1) / 64 d-cols (MMA2)
    const int lq   = lane >> 2;     // 0..7
    const int lr   = lane & 3;      // 0..3

    const int b   = blockIdx.z;
    const int i0  = blockIdx.y * BM;
    const int dc0 = blockIdx.x * DC;
    const int bTT = b * TT;

    // P write slots for this thread (cols o = wn*8 + lr*2 + {0,1}):
    const int o0 = lr * 2;
    const int ps0 = (o0 & 3) * 8 + wn * 2 + (o0 >> 2);
    const int o1 = lr * 2 + 1;
    const int ps1 = (o1 & 3) * 8 + wn * 2 + (o1 >> 2);

    // ---- prologue: Yi + tile 0 ----
    for (int idx = tid; idx < 512; idx += 256) {
        int r_ = idx >> 3, u = idx & 7;
        cp16(su + (YI_F + r_ * YSTR) * 4 + u * 16,
             g_y + (size_t)(bTT + i0 + r_) * RR + u * 4);
    }
    for (int idx = tid; idx < 2048; idx += 256) {
        int d = idx >> 3, u = idx & 7;
        cp16(su + X_F(0) * 4 + (d * YSTR + u * 4) * 4,
             g_xrp + ((size_t)(b * 64 + 0) * 1024 + dc0 + d) * 32 + u * 4);
    }
    if (tid < 256) {
        int r_ = tid >> 3, u = tid & 7;
        cp16(su + (YJ_F(0) + r_ * YSTR) * 4 + u * 16,
             g_y + (size_t)(bTT + r_) * RR + u * 4);
    }
    if (tid < 8)
        cp16(su + NJ_F(0) * 4 + tid * 16, g_n + bTT + tid * 4);
    asm volatile("cp.async.commit_group;" ::: "memory");

    float ni[2][2];
#pragma unroll
    for (int mt = 0; mt < 2; mt++) {
        ni[mt][0] = g_n[bTT + i0 + wm * 32 + mt * 16 + lq];
        ni[mt][1] = g_n[bTT + i0 + wm * 32 + mt * 16 + lq + 8];
    }

    float acc[2][8][4];
#pragma unroll
    for (int mt = 0; mt < 2; mt++)
#pragma unroll
        for (int nt = 0; nt < 8; nt++)
#pragma unroll
            for (int c = 0; c < 4; c++) acc[mt][nt][c] = 0.f;
    float lsum[2][2] = {{0.f, 0.f}, {0.f, 0.f}};

    for (int t = 0; t < NT; t++) {
        const int q = t & 1;

        asm volatile("cp.async.wait_group 0;" ::: "memory");
        __syncthreads();   // tile t visible; prior readers of buf 1-q done

        if (t + 1 < NT) {  // prefetch t+1 into buf 1-q
            for (int idx = tid; idx < 2048; idx += 256) {
                int d = idx >> 3, u = idx & 7;
                cp16(su + X_F(1 - q) * 4 + (d * YSTR + u * 4) * 4,
                     g_xrp + ((size_t)(b * 64 + t + 1) * 1024 + dc0 + d) * 32 + u * 4);
            }
            if (tid < 256) {
                int r_ = tid >> 3, u = tid & 7;
                cp16(su + (YJ_F(1 - q) + r_ * YSTR) * 4 + u * 16,
                     g_y + (size_t)(bTT + (t + 1) * BN + r_) * RR + u * 4);
            }
            if (tid < 8)
                cp16(su + NJ_F(1 - q) * 4 + tid * 16, g_n + bTT + (t + 1) * BN + tid * 4);
            asm volatile("cp.async.commit_group;" ::: "memory");
        }

        // ---- MMA1: S[32m x 8n] per warp (n = 8*wn) ----
        float S[2][4];
        {
            u32 aY[4];
            const int yjb = YJ_F(q) + (wn * 8 + lq) * YSTR + lr;
#pragma unroll
            for (int mt = 0; mt < 2; mt++)
#pragma unroll
                for (int c = 0; c < 4; c++) S[mt][c] = 0.f;
#pragma unroll
            for (int kt = 0; kt < 4; kt++) {
                u32 b0 = fu(s[yjb + kt * 8]);
                u32 b1 = fu(s[yjb + kt * 8 + 4]);
#pragma unroll
                for (int mt = 0; mt < 2; mt++) {
                    const int yib = YI_F + (wm * 32 + mt * 16 + lq) * YSTR + kt * 8 + lr;
                    aY[0] = fu(s[yib]);
                    aY[1] = fu(s[yib + 8 * YSTR]);
                    aY[2] = fu(s[yib + 4]);
                    aY[3] = fu(s[yib + 8 * YSTR + 4]);
                    mma8(S[mt], aY, b0, b1, S[mt]);
                }
            }
        }

        // ---- softmax: p = exp(2S - ni - nj); store to pair-slot sP ----
        {
            const float2 nj = *(const float2*)&s[NJ_F(q) + wn * 8 + lr * 2];
#pragma unroll
            for (int mt = 0; mt < 2; mt++) {
                float p0 = __expf(fmaf(S[mt][0], 2.f, -ni[mt][0] - nj.x));
                float p1 = __expf(fmaf(S[mt][1], 2.f, -ni[mt][0] - nj.y));
                float p2 = __expf(fmaf(S[mt][2], 2.f, -ni[mt][1] - nj.x));
                float p3 = __expf(fmaf(S[mt][3], 2.f, -ni[mt][1] - nj.y));
                lsum[mt][0] += p0 + p1;
                lsum[mt][1] += p2 + p3;
                const int ra = P_F + (wm * 32 + mt * 16 + lq) * YSTR;
                s[ra + ps0]             = p0;
                s[ra + ps1]             = p1;
                s[ra + 8 * YSTR + ps0]  = p2;
                s[ra + 8 * YSTR + ps1]  = p3;
            }
        }
        __syncthreads();   // sP visible (cross-warp exchange)

        // ---- MMA2: acc[32m x 64n] += P[32m x 32k] @ X[32k x 64n] ----
        u32 aP[2][4][4];
#pragma unroll
        for (int mt = 0; mt < 2; mt++) {
            const int ra = P_F + (wm * 32 + mt * 16 + lq) * YSTR + lr * 8;
            const float4 u0 = *(const float4*)&s[ra];
            const float4 u1 = *(const float4*)&s[ra + 4];
            const float4 v0 = *(const float4*)&s[ra + 8 * YSTR];
            const float4 v1 = *(const float4*)&s[ra + 8 * YSTR + 4];
            aP[mt][0][0] = fu(u0.x); aP[mt][0][1] = fu(v0.x);
            aP[mt][0][2] = fu(u0.y); aP[mt][0][3] = fu(v0.y);
            aP[mt][1][0] = fu(u0.z); aP[mt][1][1] = fu(v0.z);
            aP[mt][1][2] = fu(u0.w); aP[mt][1][3] = fu(v0.w);
            aP[mt][2][0] = fu(u1.x); aP[mt][2][1] = fu(v1.x);
            aP[mt][2][2] = fu(u1.y); aP[mt][2][3] = fu(v1.y);
            aP[mt][3][0] = fu(u1.z); aP[mt][3][1] = fu(v1.z);
            aP[mt][3][2] = fu(u1.w); aP[mt][3][3] = fu(v1.w);
        }
#pragma unroll
        for (int nt = 0; nt < 8; nt++) {
            const int xb = X_F(q) + (wn * 64 + nt * 8 + lq) * YSTR + lr * 8;
            const float4 xu = *(const float4*)&s[xb];
            const float4 xv = *(const float4*)&s[xb + 4];
            mma8(acc[0][nt], aP[0][0], fu(xu.x), fu(xu.y), acc[0][nt]);
            mma8(acc[1][nt], aP[1][0], fu(xu.x), fu(xu.y), acc[1][nt]);
            mma8(acc[0][nt], aP[0][1], fu(xu.z), fu(xu.w), acc[0][nt]);
            mma8(acc[1][nt], aP[1][1], fu(xu.z), fu(xu.w), acc[1][nt]);
            mma8(acc[0][nt], aP[0][2], fu(xv.x), fu(xv.y), acc[0][nt]);
            mma8(acc[1][nt], aP[1][2], fu(xv.x), fu(xv.y), acc[1][nt]);
            mma8(acc[0][nt], aP[0][3], fu(xv.z), fu(xv.w), acc[0][nt]);
            mma8(acc[1][nt], aP[1][3], fu(xv.z), fu(xv.w), acc[1][nt]);
        }
    }

    // ---- epilogue: reduce l across quad + 4 wn groups, normalize, store ----
    __syncthreads();   // done with Yi region; reuse as L
#pragma unroll
    for (int mt = 0; mt < 2; mt++)
#pragma unroll
        for (int h = 0; h < 2; h++) {
            float v = lsum[mt][h];
            v += __shfl_xor_sync(0xffffffffu, v, 1);
            v += __shfl_xor_sync(0xffffffffu, v, 2);
            if (lr == 0)
                s[L_F + wn * 64 + wm * 32 + mt * 16 + lq + 8 * h] = v;
        }
    __syncthreads();

#pragma unroll
    for (int mt = 0; mt < 2; mt++) {
#pragma unroll
        for (int h = 0; h < 2; h++) {
            const int row = wm * 32 + mt * 16 + lq + 8 * h;
            const float inv = 1.0f / (s[L_F + row] + s[L_F + 64 + row] +
                                      s[L_F + 128 + row] + s[L_F + 192 + row]);
            float* o = out + (size_t)(bTT + i0 + row) * DD + dc0 + wn * 64 + lr * 2;
#pragma unroll
            for (int nt = 0; nt < 8; nt++) {
                *(float2*)(o + nt * 8) = make_float2(acc[mt][nt][2 * h] * inv,
                                                     acc[mt][nt][2 * h + 1] * inv);
            }
        }
    }
}

extern "C" void kernel_launch(void* const* d_in, const int* in_sizes, int n_in,
                              void* d_out, int out_size) {
    const float* x = (const float*)d_in[0];   // [B,T,D] fp32
    const float* U = (const float*)d_in[1];   // [D,R]   fp32
    float* out = (float*)d_out;

    cudaFuncSetAttribute(yn_kernel, cudaFuncAttributeMaxDynamicSharedMemorySize,
                         K1_SMEM);
    yn_kernel<<<(BB * TT) / 64, 256, K1_SMEM>>>(x, U);

    cudaFuncSetAttribute(flash_kernel, cudaFuncAttributeMaxDynamicSharedMemorySize,
                         SMEM_TOTAL);
    dim3 grid(DD / DC, TT / BM, BB);
    flash_kernel<<<grid, 256, SMEM_TOTAL>>>(out);
}

// round 11
// speedup vs baseline: 1.4156x; 1.4156x over previous
#include <cuda_runtime.h>

typedef unsigned int u32;

#define BB 4
#define TT 2048
#define DD 1024
#define RR 32

// scratch (no allocations allowed)
__device__ float g_y[BB * TT * RR];      // y = x @ U (tf32-rounded)
__device__ float g_n[BB * TT];           // ||y||^2
__device__ float g_xr[BB * TT * DD];     // tf32-rna-rounded copy of x
__device__ float g_p[(size_t)BB * TT * TT];   // unnormalized probs (tf32-rounded)
__device__ float g_lp[BB * TT * 16];     // per-jtile row-sum partials

__device__ __forceinline__ u32 s2u(const void* p) {
    u32 a;
    asm("{ .reg .u64 t; cvta.to.shared.u64 t, %1; cvt.u32.u64 %0, t; }" : "=r"(a) : "l"(p));
    return a;
}
__device__ __forceinline__ void cp16(u32 dst, const void* src) {
    asm volatile("cp.async.cg.shared.global [%0], [%1], 16;" :: "r"(dst), "l"(src));
}
__device__ __forceinline__ u32 fu(float v) { return __float_as_uint(v); }
__device__ __forceinline__ float tf32f(float v) {
    u32 r;
    asm("cvt.rna.tf32.f32 %0, %1;" : "=r"(r) : "f"(v));
    return __uint_as_float(r);
}

__device__ __forceinline__ void mma8(float* d, const u32* a, u32 b0, u32 b1,
                                     const float* c) {
    asm volatile(
        "mma.sync.aligned.m16n8k8.row.col.f32.tf32.tf32.f32 "
        "{%0,%1,%2,%3}, {%4,%5,%6,%7}, {%8,%9}, {%10,%11,%12,%13};"
        : "=f"(d[0]), "=f"(d[1]), "=f"(d[2]), "=f"(d[3])
        : "r"(a[0]), "r"(a[1]), "r"(a[2]), "r"(a[3]), "r"(b0), "r"(b1),
          "f"(c[0]), "f"(c[1]), "f"(c[2]), "f"(c[3]));
}

// ---------------------------------------------------------------------------
// Kernel 1: y = x @ U (rounded), n = rowsum(y*y), g_xr = round(x).  (R6)
// ---------------------------------------------------------------------------
#define K1_XF(q) ((q) * 8192)            // [64][128] floats
#define K1_UF(q) (16384 + (q) * 4608)    // [128][36] floats
#define K1_SMEM ((16384 + 2 * 4608) * 4) // 102400 B

__global__ __launch_bounds__(256, 1) void yn_kernel(const float* __restrict__ x,
                                                    const float* __restrict__ U) {
    extern __shared__ float s[];
    const u32 su = s2u(s);

    const int tid  = threadIdx.x;
    const int w    = tid >> 5;
    const int lane = tid & 31;
    const int row0 = blockIdx.x * 64;

    for (int idx = tid; idx < 2048; idx += 256) {
        int r_ = idx >> 5, u = idx & 31;
        cp16(su + K1_XF(0) * 4 + (r_ * 128 + u * 4) * 4,
             x + (size_t)(row0 + r_) * DD + u * 4);
    }
    for (int idx = tid; idx < 1024; idx += 256) {
        int d = idx >> 3, u = idx & 7;
        cp16(su + K1_UF(0) * 4 + (d * 36 + u * 4) * 4,
             U + (size_t)d * RR + u * 4);
    }
    asm volatile("cp.async.commit_group;" ::: "memory");

    float acc[8];
#pragma unroll
    for (int k = 0; k < 8; k++) acc[k] = 0.f;

    for (int c = 0; c < 8; c++) {
        const int q = c & 1;
        asm volatile("cp.async.wait_group 0;" ::: "memory");
        __syncthreads();

        if (c + 1 < 8) {
            const int d0n = (c + 1) * 128;
            for (int idx = tid; idx < 2048; idx += 256) {
                int r_ = idx >> 5, u = idx & 31;
                cp16(su + K1_XF(1 - q) * 4 + (r_ * 128 + u * 4) * 4,
                     x + (size_t)(row0 + r_) * DD + d0n + u * 4);
            }
            for (int idx = tid; idx < 1024; idx += 256) {
                int d = idx >> 3, u = idx & 7;
                cp16(su + K1_UF(1 - q) * 4 + ((d * 36 + u * 4)) * 4,
                     U + (size_t)(d0n + d) * RR + u * 4);
            }
            asm volatile("cp.async.commit_group;" ::: "memory");
        }

        const float* sX = s + K1_XF(q);
        const float* sU = s + K1_UF(q);
#pragma unroll
        for (int dd4 = 0; dd4 < 32; dd4++) {
            float u0 = sU[(dd4 * 4 + 0) * 36 + lane];
            float u1 = sU[(dd4 * 4 + 1) * 36 + lane];
            float u2 = sU[(dd4 * 4 + 2) * 36 + lane];
            float u3 = sU[(dd4 * 4 + 3) * 36 + lane];
#pragma unroll
            for (int k = 0; k < 8; k++) {
                const float4 xv = *(const float4*)&sX[(w * 8 + k) * 128 + dd4 * 4];
                acc[k] = fmaf(xv.x, u0, acc[k]);
                acc[k] = fmaf(xv.y, u1, acc[k]);
                acc[k] = fmaf(xv.z, u2, acc[k]);
                acc[k] = fmaf(xv.w, u3, acc[k]);
            }
        }

        const int d0 = c * 128;
        for (int idx = tid; idx < 2048; idx += 256) {
            int r_ = idx >> 5, u = idx & 31;
            float4 xv = *(const float4*)&sX[r_ * 128 + u * 4];
            xv.x = tf32f(xv.x); xv.y = tf32f(xv.y);
            xv.z = tf32f(xv.z); xv.w = tf32f(xv.w);
            *(float4*)&g_xr[(size_t)(row0 + r_) * DD + d0 + u * 4] = xv;
        }
    }

#pragma unroll
    for (int k = 0; k < 8; k++) {
        int rg = row0 + w * 8 + k;
        float ar = tf32f(acc[k]);
        g_y[(size_t)rg * RR + lane] = ar;
        float v = ar * ar;
#pragma unroll
        for (int off = 16; off; off >>= 1)
            v += __shfl_xor_sync(0xffffffffu, v, off);
        if (lane == 0) g_n[rg] = v;
    }
}

// ---------------------------------------------------------------------------
// Kernel 2 (pk): P̂ = exp(2 Yi.Yj^T - ni - nj), tf32-rounded, + row partials.
// CTA = 128i x 128j; 8 warps = 4 wm x 2 wn; warp tile 32i x 64j.
// ---------------------------------------------------------------------------
#define PK_YI 0        // [128][36]
#define PK_YJ 4608     // [128][36]
#define PK_NJ 9216     // [128]
#define PK_SL 9344     // [2][128]
#define PK_SMEM ((9344 + 256) * 4)
#define YSTR 36

__global__ __launch_bounds__(256, 2) void pk_kernel() {
    extern __shared__ float s[];
    const u32 su = s2u(s);

    const int tid  = threadIdx.x;
    const int w    = tid >> 5;
    const int lane = tid & 31;
    const int wm   = w >> 1;        // 0..3
    const int wn   = w & 1;         // 0..1
    const int lq   = lane >> 2;
    const int lr   = lane & 3;

    const int b   = blockIdx.z;
    const int i0  = blockIdx.y * 128;
    const int j0  = blockIdx.x * 128;
    const int bTT = b * TT;

    for (int idx = tid; idx < 1024; idx += 256) {
        int r_ = idx >> 3, u = idx & 7;
        cp16(su + (PK_YI + r_ * YSTR) * 4 + u * 16,
             g_y + (size_t)(bTT + i0 + r_) * RR + u * 4);
        cp16(su + (PK_YJ + r_ * YSTR) * 4 + u * 16,
             g_y + (size_t)(bTT + j0 + r_) * RR + u * 4);
    }
    if (tid < 32) cp16(su + PK_NJ * 4 + tid * 16, g_n + bTT + j0 + tid * 4);
    asm volatile("cp.async.commit_group;" ::: "memory");
    asm volatile("cp.async.wait_group 0;" ::: "memory");
    __syncthreads();

    float ni[2][2];
#pragma unroll
    for (int mt = 0; mt < 2; mt++) {
        ni[mt][0] = g_n[bTT + i0 + wm * 32 + mt * 16 + lq];
        ni[mt][1] = g_n[bTT + i0 + wm * 32 + mt * 16 + lq + 8];
    }

    float S[2][8][4];
#pragma unroll
    for (int mt = 0; mt < 2; mt++)
#pragma unroll
        for (int nt = 0; nt < 8; nt++)
#pragma unroll
            for (int c = 0; c < 4; c++) S[mt][nt][c] = 0.f;

#pragma unroll
    for (int kt = 0; kt < 4; kt++) {
        u32 aY[2][4];
#pragma unroll
        for (int mt = 0; mt < 2; mt++) {
            const int yib = PK_YI + (wm * 32 + mt * 16 + lq) * YSTR + kt * 8 + lr;
            aY[mt][0] = fu(s[yib]);
            aY[mt][1] = fu(s[yib + 8 * YSTR]);
            aY[mt][2] = fu(s[yib + 4]);
            aY[mt][3] = fu(s[yib + 8 * YSTR + 4]);
        }
#pragma unroll
        for (int nt = 0; nt < 8; nt++) {
            const int yjb = PK_YJ + (wn * 64 + nt * 8 + lq) * YSTR + kt * 8 + lr;
            u32 b0 = fu(s[yjb]);
            u32 b1 = fu(s[yjb + 4]);
            mma8(S[0][nt], aY[0], b0, b1, S[0][nt]);
            mma8(S[1][nt], aY[1], b0, b1, S[1][nt]);
        }
    }

    float lsum[2][2] = {{0.f, 0.f}, {0.f, 0.f}};
#pragma unroll
    for (int mt = 0; mt < 2; mt++) {
#pragma unroll
        for (int nt = 0; nt < 8; nt++) {
            const float2 nj = *(const float2*)&s[PK_NJ + wn * 64 + nt * 8 + lr * 2];
            float p0 = tf32f(__expf(fmaf(S[mt][nt][0], 2.f, -ni[mt][0] - nj.x)));
            float p1 = tf32f(__expf(fmaf(S[mt][nt][1], 2.f, -ni[mt][0] - nj.y)));
            float p2 = tf32f(__expf(fmaf(S[mt][nt][2], 2.f, -ni[mt][1] - nj.x)));
            float p3 = tf32f(__expf(fmaf(S[mt][nt][3], 2.f, -ni[mt][1] - nj.y)));
            lsum[mt][0] += p0 + p1;
            lsum[mt][1] += p2 + p3;
            const size_t r0 = (size_t)(bTT + i0 + wm * 32 + mt * 16 + lq) * TT
                              + j0 + wn * 64 + nt * 8 + lr * 2;
            *(float2*)&g_p[r0]          = make_float2(p0, p1);
            *(float2*)&g_p[r0 + 8 * TT] = make_float2(p2, p3);
        }
    }

    // row partials: quad-reduce, stage by wn, combine, write g_lp
#pragma unroll
    for (int mt = 0; mt < 2; mt++)
#pragma unroll
        for (int h = 0; h < 2; h++) {
            float v = lsum[mt][h];
            v += __shfl_xor_sync(0xffffffffu, v, 1);
            v += __shfl_xor_sync(0xffffffffu, v, 2);
            if (lr == 0)
                s[PK_SL + wn * 128 + wm * 32 + mt * 16 + lq + 8 * h] = v;
        }
    __syncthreads();
    if (tid < 128) {
        g_lp[(size_t)(bTT + i0 + tid) * 16 + blockIdx.x] =
            s[PK_SL + tid] + s[PK_SL + 128 + tid];
    }
}

// ---------------------------------------------------------------------------
// Kernel 3 (gemm2): out = (P̂ @ xr) / l.  Pure GEMM, R6 MMA2 mainloop.
// CTA = 64m x 256n; 8 warps = 2 wm x 4 wn; warp 32m x 64n; 2 CTAs/SM.
// ---------------------------------------------------------------------------
#define A_F(q) ((q) * 2304)             // [64][36] x2
#define X_F(q) (4608 + (q) * 8448)      // [32][264] x2
#define G2_SMEM ((4608 + 2 * 8448) * 4) // 86016 B
#define XSTR 264
#define G2NT 64                          // k tiles of 32

__global__ __launch_bounds__(256, 2) void gemm2_kernel(float* __restrict__ out) {
    extern __shared__ float s[];
    const u32 su = s2u(s);

    const int tid  = threadIdx.x;
    const int w    = tid >> 5;
    const int lane = tid & 31;
    const int wm   = w >> 2;        // 0..1
    const int wn   = w & 3;         // 0..3
    const int lq   = lane >> 2;
    const int lr   = lane & 3;

    const int b   = blockIdx.z;
    const int m0  = blockIdx.y * 64;
    const int dc0 = blockIdx.x * 256;
    const int bTT = b * TT;

    // ---- prologue: k-tile 0 ----
    for (int idx = tid; idx < 512; idx += 256) {
        int r_ = idx >> 3, u = idx & 7;
        cp16(su + A_F(0) * 4 + (r_ * YSTR + u * 4) * 4,
             g_p + (size_t)(bTT + m0 + r_) * TT + u * 4);
    }
    for (int idx = tid; idx < 2048; idx += 256) {
        int r_ = idx >> 6, u = idx & 63;
        cp16(su + X_F(0) * 4 + (r_ * XSTR + u * 4) * 4,
             g_xr + (size_t)(bTT + r_) * DD + dc0 + u * 4);
    }
    asm volatile("cp.async.commit_group;" ::: "memory");

    float acc[2][8][4];
#pragma unroll
    for (int mt = 0; mt < 2; mt++)
#pragma unroll
        for (int nt = 0; nt < 8; nt++)
#pragma unroll
            for (int c = 0; c < 4; c++) acc[mt][nt][c] = 0.f;

    for (int t = 0; t < G2NT; t++) {
        const int q = t & 1;

        asm volatile("cp.async.wait_group 0;" ::: "memory");
        __syncthreads();

        if (t + 1 < G2NT) {
            const int k0n = (t + 1) * 32;
            for (int idx = tid; idx < 512; idx += 256) {
                int r_ = idx >> 3, u = idx & 7;
                cp16(su + A_F(1 - q) * 4 + (r_ * YSTR + u * 4) * 4,
                     g_p + (size_t)(bTT + m0 + r_) * TT + k0n + u * 4);
            }
            for (int idx = tid; idx < 2048; idx += 256) {
                int r_ = idx >> 6, u = idx & 63;
                cp16(su + X_F(1 - q) * 4 + (r_ * XSTR + u * 4) * 4,
                     g_xr + (size_t)(bTT + k0n + r_) * DD + dc0 + u * 4);
            }
            asm volatile("cp.async.commit_group;" ::: "memory");
        }

        // A fragments (P rows)
        u32 aP[2][4][4];
#pragma unroll
        for (int mt = 0; mt < 2; mt++) {
            const int pab = A_F(q) + (wm * 32 + mt * 16 + lq) * YSTR + lr;
#pragma unroll
            for (int kt = 0; kt < 4; kt++) {
                aP[mt][kt][0] = fu(s[pab + kt * 8]);
                aP[mt][kt][1] = fu(s[pab + kt * 8 + 8 * YSTR]);
                aP[mt][kt][2] = fu(s[pab + kt * 8 + 4]);
                aP[mt][kt][3] = fu(s[pab + kt * 8 + 8 * YSTR + 4]);
            }
        }
        const int xb = X_F(q) + lr * XSTR + wn * 64 + lq;
#pragma unroll
        for (int nt = 0; nt < 8; nt++) {
#pragma unroll
            for (int kt = 0; kt < 4; kt++) {
                u32 b0 = fu(s[xb + kt * 8 * XSTR + nt * 8]);
                u32 b1 = fu(s[xb + (kt * 8 + 4) * XSTR + nt * 8]);
                mma8(acc[0][nt], aP[0][kt], b0, b1, acc[0][nt]);
                mma8(acc[1][nt], aP[1][kt], b0, b1, acc[1][nt]);
            }
        }
    }

    // ---- epilogue: normalize by l = sum of 16 partials, store ----
#pragma unroll
    for (int mt = 0; mt < 2; mt++) {
#pragma unroll
        for (int h = 0; h < 2; h++) {
            const int row = wm * 32 + mt * 16 + lq + 8 * h;
            const float* lp = &g_lp[(size_t)(bTT + m0 + row) * 16];
            const float4 a0 = *(const float4*)(lp + 0);
            const float4 a1 = *(const float4*)(lp + 4);
            const float4 a2 = *(const float4*)(lp + 8);
            const float4 a3 = *(const float4*)(lp + 12);
            const float l = ((a0.x + a0.y) + (a0.z + a0.w)) +
                            ((a1.x + a1.y) + (a1.z + a1.w)) +
                            ((a2.x + a2.y) + (a2.z + a2.w)) +
                            ((a3.x + a3.y) + (a3.z + a3.w));
            const float inv = 1.0f / l;
            float* o = out + (size_t)(bTT + m0 + row) * DD + dc0 + wn * 64 + lr * 2;
#pragma unroll
            for (int nt = 0; nt < 8; nt++) {
                *(float2*)(o + nt * 8) = make_float2(acc[mt][nt][2 * h] * inv,
                                                     acc[mt][nt][2 * h + 1] * inv);
            }
        }
    }
}

extern "C" void kernel_launch(void* const* d_in, const int* in_sizes, int n_in,
                              void* d_out, int out_size) {
    const float* x = (const float*)d_in[0];   // [B,T,D] fp32
    const float* U = (const float*)d_in[1];   // [D,R]   fp32
    float* out = (float*)d_out;

    cudaFuncSetAttribute(yn_kernel, cudaFuncAttributeMaxDynamicSharedMemorySize,
                         K1_SMEM);
    yn_kernel<<<(BB * TT) / 64, 256, K1_SMEM>>>(x, U);

    dim3 gpk(TT / 128, TT / 128, BB);
    pk_kernel<<<gpk, 256, PK_SMEM>>>();

    cudaFuncSetAttribute(gemm2_kernel, cudaFuncAttributeMaxDynamicSharedMemorySize,
                         G2_SMEM);
    dim3 g2(DD / 256, TT / 64, BB);
    gemm2_kernel<<<g2, 256, G2_SMEM>>>(out);
}

// round 12
// speedup vs baseline: 4.8860x; 3.4515x over previous
#include <cuda_runtime.h>

typedef unsigned int u32;

#define BB 4
#define TT 2048
#define DD 1024
#define RR 32

// scratch (no allocations allowed)
__device__ float g_y[BB * TT * RR];      // y = x @ U (tf32-rounded)
__device__ float g_n[BB * TT];           // ||y||^2
__device__ float g_xr[BB * TT * DD];     // tf32-rna-rounded copy of x
__device__ float g_p[(size_t)BB * TT * TT];   // unnormalized probs (tf32-rounded)
__device__ float g_lp[BB * TT * 16];     // per-jtile row-sum partials
__device__ int   g_flag[BB * 32 * 64];   // [b][mtile(64 rows)][ktile(32 keys)]

__device__ __forceinline__ u32 s2u(const void* p) {
    u32 a;
    asm("{ .reg .u64 t; cvta.to.shared.u64 t, %1; cvt.u32.u64 %0, t; }" : "=r"(a) : "l"(p));
    return a;
}
__device__ __forceinline__ void cp16(u32 dst, const void* src) {
    asm volatile("cp.async.cg.shared.global [%0], [%1], 16;" :: "r"(dst), "l"(src));
}
__device__ __forceinline__ u32 fu(float v) { return __float_as_uint(v); }
__device__ __forceinline__ float tf32f(float v) {
    u32 r;
    asm("cvt.rna.tf32.f32 %0, %1;" : "=r"(r) : "f"(v));
    return __uint_as_float(r);
}

__device__ __forceinline__ void mma8(float* d, const u32* a, u32 b0, u32 b1,
                                     const float* c) {
    asm volatile(
        "mma.sync.aligned.m16n8k8.row.col.f32.tf32.tf32.f32 "
        "{%0,%1,%2,%3}, {%4,%5,%6,%7}, {%8,%9}, {%10,%11,%12,%13};"
        : "=f"(d[0]), "=f"(d[1]), "=f"(d[2]), "=f"(d[3])
        : "r"(a[0]), "r"(a[1]), "r"(a[2]), "r"(a[3]), "r"(b0), "r"(b1),
          "f"(c[0]), "f"(c[1]), "f"(c[2]), "f"(c[3]));
}

// ---------------------------------------------------------------------------
// Kernel 1: y = x @ U (rounded), n = rowsum(y*y), g_xr = round(x).
// 32 rows/CTA, grid 256, double-buffered 128-d chunks.
// ---------------------------------------------------------------------------
#define K1_XF(q) ((q) * 4096)            // [32][128] floats
#define K1_UF(q) (8192 + (q) * 4608)     // [128][36] floats
#define K1_SMEM ((8192 + 2 * 4608) * 4)  // 69632 B

__global__ __launch_bounds__(256, 1) void yn_kernel(const float* __restrict__ x,
                                                    const float* __restrict__ U) {
    extern __shared__ float s[];
    const u32 su = s2u(s);

    const int tid  = threadIdx.x;
    const int w    = tid >> 5;
    const int lane = tid & 31;
    const int row0 = blockIdx.x * 32;

    for (int idx = tid; idx < 1024; idx += 256) {
        int r_ = idx >> 5, u = idx & 31;
        cp16(su + K1_XF(0) * 4 + (r_ * 128 + u * 4) * 4,
             x + (size_t)(row0 + r_) * DD + u * 4);
    }
    for (int idx = tid; idx < 1024; idx += 256) {
        int d = idx >> 3, u = idx & 7;
        cp16(su + K1_UF(0) * 4 + (d * 36 + u * 4) * 4,
             U + (size_t)d * RR + u * 4);
    }
    asm volatile("cp.async.commit_group;" ::: "memory");

    float acc[4];
#pragma unroll
    for (int k = 0; k < 4; k++) acc[k] = 0.f;

    for (int c = 0; c < 8; c++) {
        const int q = c & 1;
        asm volatile("cp.async.wait_group 0;" ::: "memory");
        __syncthreads();

        if (c + 1 < 8) {
            const int d0n = (c + 1) * 128;
            for (int idx = tid; idx < 1024; idx += 256) {
                int r_ = idx >> 5, u = idx & 31;
                cp16(su + K1_XF(1 - q) * 4 + (r_ * 128 + u * 4) * 4,
                     x + (size_t)(row0 + r_) * DD + d0n + u * 4);
            }
            for (int idx = tid; idx < 1024; idx += 256) {
                int d = idx >> 3, u = idx & 7;
                cp16(su + K1_UF(1 - q) * 4 + ((d * 36 + u * 4)) * 4,
                     U + (size_t)(d0n + d) * RR + u * 4);
            }
            asm volatile("cp.async.commit_group;" ::: "memory");
        }

        const float* sX = s + K1_XF(q);
        const float* sU = s + K1_UF(q);
#pragma unroll
        for (int dd4 = 0; dd4 < 32; dd4++) {
            float u0 = sU[(dd4 * 4 + 0) * 36 + lane];
            float u1 = sU[(dd4 * 4 + 1) * 36 + lane];
            float u2 = sU[(dd4 * 4 + 2) * 36 + lane];
            float u3 = sU[(dd4 * 4 + 3) * 36 + lane];
#pragma unroll
            for (int k = 0; k < 4; k++) {
                const float4 xv = *(const float4*)&sX[(w * 4 + k) * 128 + dd4 * 4];
                acc[k] = fmaf(xv.x, u0, acc[k]);
                acc[k] = fmaf(xv.y, u1, acc[k]);
                acc[k] = fmaf(xv.z, u2, acc[k]);
                acc[k] = fmaf(xv.w, u3, acc[k]);
            }
        }

        const int d0 = c * 128;
        for (int idx = tid; idx < 1024; idx += 256) {
            int r_ = idx >> 5, u = idx & 31;
            float4 xv = *(const float4*)&sX[r_ * 128 + u * 4];
            xv.x = tf32f(xv.x); xv.y = tf32f(xv.y);
            xv.z = tf32f(xv.z); xv.w = tf32f(xv.w);
            *(float4*)&g_xr[(size_t)(row0 + r_) * DD + d0 + u * 4] = xv;
        }
    }

#pragma unroll
    for (int k = 0; k < 4; k++) {
        int rg = row0 + w * 4 + k;
        float ar = tf32f(acc[k]);
        g_y[(size_t)rg * RR + lane] = ar;
        float v = ar * ar;
#pragma unroll
        for (int off = 16; off; off >>= 1)
            v += __shfl_xor_sync(0xffffffffu, v, off);
        if (lane == 0) g_n[rg] = v;
    }
}

// ---------------------------------------------------------------------------
// Kernel 2 (pk): P̂ = exp(2 Yi.Yj^T - ni - nj), tf32-rounded, + row partials
// + block-sparsity flags. CTA 128i x 128j; 8 warps = 4 wm x 2 wn.
// Dead (arg < -25 everywhere) 16x32 groups skip MUFU entirely.
// ---------------------------------------------------------------------------
#define PK_YI 0        // [128][36]
#define PK_YJ 4608     // [128][36]
#define PK_NJ 9216     // [128]
#define PK_FL 9344     // 8 ints
#define PK_SL 9352     // [2][128]
#define PK_SMEM ((9352 + 256) * 4)
#define YSTR 36

__global__ __launch_bounds__(256, 2) void pk_kernel() {
    extern __shared__ float s[];
    const u32 su = s2u(s);
    int* sflag = (int*)s + PK_FL;

    const int tid  = threadIdx.x;
    const int w    = tid >> 5;
    const int lane = tid & 31;
    const int wm   = w >> 1;        // 0..3
    const int wn   = w & 1;         // 0..1
    const int lq   = lane >> 2;
    const int lr   = lane & 3;

    const int b   = blockIdx.z;
    const int i0  = blockIdx.y * 128;
    const int j0  = blockIdx.x * 128;
    const int bTT = b * TT;

    for (int idx = tid; idx < 1024; idx += 256) {
        int r_ = idx >> 3, u = idx & 7;
        cp16(su + (PK_YI + r_ * YSTR) * 4 + u * 16,
             g_y + (size_t)(bTT + i0 + r_) * RR + u * 4);
        cp16(su + (PK_YJ + r_ * YSTR) * 4 + u * 16,
             g_y + (size_t)(bTT + j0 + r_) * RR + u * 4);
    }
    if (tid < 32) cp16(su + PK_NJ * 4 + tid * 16, g_n + bTT + j0 + tid * 4);
    if (tid < 8) sflag[tid] = 0;
    asm volatile("cp.async.commit_group;" ::: "memory");
    asm volatile("cp.async.wait_group 0;" ::: "memory");
    __syncthreads();

    float ni[2][2];
#pragma unroll
    for (int mt = 0; mt < 2; mt++) {
        ni[mt][0] = g_n[bTT + i0 + wm * 32 + mt * 16 + lq];
        ni[mt][1] = g_n[bTT + i0 + wm * 32 + mt * 16 + lq + 8];
    }

    float S[2][8][4];
#pragma unroll
    for (int mt = 0; mt < 2; mt++)
#pragma unroll
        for (int nt = 0; nt < 8; nt++)
#pragma unroll
            for (int c = 0; c < 4; c++) S[mt][nt][c] = 0.f;

#pragma unroll
    for (int kt = 0; kt < 4; kt++) {
        u32 aY[2][4];
#pragma unroll
        for (int mt = 0; mt < 2; mt++) {
            const int yib = PK_YI + (wm * 32 + mt * 16 + lq) * YSTR + kt * 8 + lr;
            aY[mt][0] = fu(s[yib]);
            aY[mt][1] = fu(s[yib + 8 * YSTR]);
            aY[mt][2] = fu(s[yib + 4]);
            aY[mt][3] = fu(s[yib + 8 * YSTR + 4]);
        }
#pragma unroll
        for (int nt = 0; nt < 8; nt++) {
            const int yjb = PK_YJ + (wn * 64 + nt * 8 + lq) * YSTR + kt * 8 + lr;
            u32 b0 = fu(s[yjb]);
            u32 b1 = fu(s[yjb + 4]);
            mma8(S[0][nt], aY[0], b0, b1, S[0][nt]);
            mma8(S[1][nt], aY[1], b0, b1, S[1][nt]);
        }
    }

    // ---- convert S -> arg = 2S - ni - nj (in place) ----
#pragma unroll
    for (int mt = 0; mt < 2; mt++) {
#pragma unroll
        for (int nt = 0; nt < 8; nt++) {
            const float2 nj = *(const float2*)&s[PK_NJ + wn * 64 + nt * 8 + lr * 2];
            S[mt][nt][0] = fmaf(S[mt][nt][0], 2.f, -ni[mt][0] - nj.x);
            S[mt][nt][1] = fmaf(S[mt][nt][1], 2.f, -ni[mt][0] - nj.y);
            S[mt][nt][2] = fmaf(S[mt][nt][2], 2.f, -ni[mt][1] - nj.x);
            S[mt][nt][3] = fmaf(S[mt][nt][3], 2.f, -ni[mt][1] - nj.y);
        }
    }

    // ---- per (mt, 32-col group) exact max -> activity ----
    bool act[2][2];
#pragma unroll
    for (int mt = 0; mt < 2; mt++) {
#pragma unroll
        for (int G = 0; G < 2; G++) {
            float m_ = -1e30f;
#pragma unroll
            for (int nt = G * 4; nt < G * 4 + 4; nt++)
#pragma unroll
                for (int c = 0; c < 4; c++) m_ = fmaxf(m_, S[mt][nt][c]);
#pragma unroll
            for (int off = 16; off; off >>= 1)
                m_ = fmaxf(m_, __shfl_xor_sync(0xffffffffu, m_, off));
            act[mt][G] = (m_ > -25.0f);
            if (act[mt][G] && lane == 0)
                sflag[(wm >> 1) * 4 + wn * 2 + G] = 1;
        }
    }

    // ---- exp only for active groups; store p (zeros otherwise) ----
    float lsum[2][2] = {{0.f, 0.f}, {0.f, 0.f}};
#pragma unroll
    for (int mt = 0; mt < 2; mt++) {
#pragma unroll
        for (int G = 0; G < 2; G++) {
            if (act[mt][G]) {
#pragma unroll
                for (int nt = G * 4; nt < G * 4 + 4; nt++) {
                    float p0 = tf32f(__expf(S[mt][nt][0]));
                    float p1 = tf32f(__expf(S[mt][nt][1]));
                    float p2 = tf32f(__expf(S[mt][nt][2]));
                    float p3 = tf32f(__expf(S[mt][nt][3]));
                    lsum[mt][0] += p0 + p1;
                    lsum[mt][1] += p2 + p3;
                    const size_t r0 = (size_t)(bTT + i0 + wm * 32 + mt * 16 + lq) * TT
                                      + j0 + wn * 64 + nt * 8 + lr * 2;
                    *(float2*)&g_p[r0]          = make_float2(p0, p1);
                    *(float2*)&g_p[r0 + 8 * TT] = make_float2(p2, p3);
                }
            } else {
#pragma unroll
                for (int nt = G * 4; nt < G * 4 + 4; nt++) {
                    const size_t r0 = (size_t)(bTT + i0 + wm * 32 + mt * 16 + lq) * TT
                                      + j0 + wn * 64 + nt * 8 + lr * 2;
                    *(float2*)&g_p[r0]          = make_float2(0.f, 0.f);
                    *(float2*)&g_p[r0 + 8 * TT] = make_float2(0.f, 0.f);
                }
            }
        }
    }

    // ---- row partials + flags out ----
#pragma unroll
    for (int mt = 0; mt < 2; mt++)
#pragma unroll
        for (int h = 0; h < 2; h++) {
            float v = lsum[mt][h];
            v += __shfl_xor_sync(0xffffffffu, v, 1);
            v += __shfl_xor_sync(0xffffffffu, v, 2);
            if (lr == 0)
                s[PK_SL + wn * 128 + wm * 32 + mt * 16 + lq + 8 * h] = v;
        }
    __syncthreads();
    if (tid < 128) {
        g_lp[(size_t)(bTT + i0 + tid) * 16 + blockIdx.x] =
            s[PK_SL + tid] + s[PK_SL + 128 + tid];
    }
    if (tid < 8) {
        const int mtile = (i0 >> 6) + (tid >> 2);
        const int kt    = (j0 >> 5) + (tid & 3);
        g_flag[(b * 32 + mtile) * 64 + kt] = sflag[tid];
    }
}

// ---------------------------------------------------------------------------
// Kernel 3 (gemm2): out = (P̂ @ xr) / l, visiting only flagged k-tiles.
// CTA = 64m x 256n; 8 warps = 2 wm x 4 wn; warp 32m x 64n; 2 CTAs/SM.
// ---------------------------------------------------------------------------
#define A_F(q) ((q) * 2304)             // [64][36] x2
#define X_F(q) (4608 + (q) * 8448)      // [32][264] x2
#define G2_SMEM ((4608 + 2 * 8448) * 4) // 86016 B
#define XSTR 264

#define G2_LOAD(tt, qq) do {                                                   \
    for (int idx = tid; idx < 512; idx += 256) {                               \
        int r_ = idx >> 3, u = idx & 7;                                        \
        cp16(su + A_F(qq) * 4 + (r_ * YSTR + u * 4) * 4,                       \
             g_p + (size_t)(bTT + m0 + r_) * TT + (tt) * 32 + u * 4);          \
    }                                                                          \
    for (int idx = tid; idx < 2048; idx += 256) {                              \
        int r_ = idx >> 6, u = idx & 63;                                       \
        cp16(su + X_F(qq) * 4 + (r_ * XSTR + u * 4) * 4,                       \
             g_xr + (size_t)(bTT + (tt) * 32 + r_) * DD + dc0 + u * 4);        \
    }                                                                          \
    asm volatile("cp.async.commit_group;" ::: "memory");                       \
} while (0)

__global__ __launch_bounds__(256, 2) void gemm2_kernel(float* __restrict__ out) {
    extern __shared__ float s[];
    const u32 su = s2u(s);

    const int tid  = threadIdx.x;
    const int w    = tid >> 5;
    const int lane = tid & 31;
    const int wm   = w >> 2;        // 0..1
    const int wn   = w & 3;         // 0..3
    const int lq   = lane >> 2;
    const int lr   = lane & 3;

    const int b   = blockIdx.z;
    const int m0  = blockIdx.y * 64;
    const int dc0 = blockIdx.x * 256;
    const int bTT = b * TT;

    const int* fb = &g_flag[(b * 32 + (m0 >> 6)) * 64];

    float acc[2][8][4];
#pragma unroll
    for (int mt = 0; mt < 2; mt++)
#pragma unroll
        for (int nt = 0; nt < 8; nt++)
#pragma unroll
            for (int c = 0; c < 4; c++) acc[mt][nt][c] = 0.f;

    int t = 0;
    while (t < 64 && fb[t] == 0) t++;
    int q = 0;
    if (t < 64) G2_LOAD(t, 0);

    while (t < 64) {
        int tn = t + 1;
        while (tn < 64 && fb[tn] == 0) tn++;

        asm volatile("cp.async.wait_group 0;" ::: "memory");
        __syncthreads();

        if (tn < 64) G2_LOAD(tn, 1 - q);

        // A fragments (P rows)
        u32 aP[2][4][4];
#pragma unroll
        for (int mt = 0; mt < 2; mt++) {
            const int pab = A_F(q) + (wm * 32 + mt * 16 + lq) * YSTR + lr;
#pragma unroll
            for (int kt = 0; kt < 4; kt++) {
                aP[mt][kt][0] = fu(s[pab + kt * 8]);
                aP[mt][kt][1] = fu(s[pab + kt * 8 + 8 * YSTR]);
                aP[mt][kt][2] = fu(s[pab + kt * 8 + 4]);
                aP[mt][kt][3] = fu(s[pab + kt * 8 + 8 * YSTR + 4]);
            }
        }
        const int xb = X_F(q) + lr * XSTR + wn * 64 + lq;
#pragma unroll
        for (int nt = 0; nt < 8; nt++) {
#pragma unroll
            for (int kt = 0; kt < 4; kt++) {
                u32 b0 = fu(s[xb + kt * 8 * XSTR + nt * 8]);
                u32 b1 = fu(s[xb + (kt * 8 + 4) * XSTR + nt * 8]);
                mma8(acc[0][nt], aP[0][kt], b0, b1, acc[0][nt]);
                mma8(acc[1][nt], aP[1][kt], b0, b1, acc[1][nt]);
            }
        }

        q ^= 1;
        t = tn;
    }

    // ---- epilogue: normalize by l = sum of 16 partials, store ----
#pragma unroll
    for (int mt = 0; mt < 2; mt++) {
#pragma unroll
        for (int h = 0; h < 2; h++) {
            const int row = wm * 32 + mt * 16 + lq + 8 * h;
            const float* lp = &g_lp[(size_t)(bTT + m0 + row) * 16];
            const float4 a0 = *(const float4*)(lp + 0);
            const float4 a1 = *(const float4*)(lp + 4);
            const float4 a2 = *(const float4*)(lp + 8);
            const float4 a3 = *(const float4*)(lp + 12);
            const float l = ((a0.x + a0.y) + (a0.z + a0.w)) +
                            ((a1.x + a1.y) + (a1.z + a1.w)) +
                            ((a2.x + a2.y) + (a2.z + a2.w)) +
                            ((a3.x + a3.y) + (a3.z + a3.w));
            const float inv = 1.0f / l;
            float* o = out + (size_t)(bTT + m0 + row) * DD + dc0 + wn * 64 + lr * 2;
#pragma unroll
            for (int nt = 0; nt < 8; nt++) {
                *(float2*)(o + nt * 8) = make_float2(acc[mt][nt][2 * h] * inv,
                                                     acc[mt][nt][2 * h + 1] * inv);
            }
        }
    }
}

extern "C" void kernel_launch(void* const* d_in, const int* in_sizes, int n_in,
                              void* d_out, int out_size) {
    const float* x = (const float*)d_in[0];   // [B,T,D] fp32
    const float* U = (const float*)d_in[1];   // [D,R]   fp32
    float* out = (float*)d_out;

    cudaFuncSetAttribute(yn_kernel, cudaFuncAttributeMaxDynamicSharedMemorySize,
                         K1_SMEM);
    yn_kernel<<<(BB * TT) / 32, 256, K1_SMEM>>>(x, U);

    dim3 gpk(TT / 128, TT / 128, BB);
    pk_kernel<<<gpk, 256, PK_SMEM>>>();

    cudaFuncSetAttribute(gemm2_kernel, cudaFuncAttributeMaxDynamicSharedMemorySize,
                         G2_SMEM);
    dim3 g2(DD / 256, TT / 64, BB);
    gemm2_kernel<<<g2, 256, G2_SMEM>>>(out);
}

// round 13
// speedup vs baseline: 7.6452x; 1.5647x over previous
#include <cuda_runtime.h>

typedef unsigned int u32;

#define BB 4
#define TT 2048
#define DD 1024
#define RR 32

// scratch (no allocations allowed)
__device__ float g_y[BB * TT * RR];      // y = x @ U (tf32-rounded)
__device__ float g_n[BB * TT];           // ||y||^2
__device__ float g_p[(size_t)BB * TT * TT];   // unnormalized probs (tf32-rounded)
__device__ float g_lp[BB * TT * 16];     // per-jtile row-sum partials
__device__ int   g_flag[BB * 32 * 64];   // [b][mtile(64 rows)][ktile(32 keys)]

__device__ __forceinline__ u32 s2u(const void* p) {
    u32 a;
    asm("{ .reg .u64 t; cvta.to.shared.u64 t, %1; cvt.u32.u64 %0, t; }" : "=r"(a) : "l"(p));
    return a;
}
__device__ __forceinline__ void cp16(u32 dst, const void* src) {
    asm volatile("cp.async.cg.shared.global [%0], [%1], 16;" :: "r"(dst), "l"(src));
}
__device__ __forceinline__ u32 fu(float v) { return __float_as_uint(v); }
__device__ __forceinline__ float tf32f(float v) {
    u32 r;
    asm("cvt.rna.tf32.f32 %0, %1;" : "=r"(r) : "f"(v));
    return __uint_as_float(r);
}
__device__ __forceinline__ u32 tf32u(float v) {
    u32 r;
    asm("cvt.rna.tf32.f32 %0, %1;" : "=r"(r) : "f"(v));
    return r;
}

__device__ __forceinline__ void mma8(float* d, const u32* a, u32 b0, u32 b1,
                                     const float* c) {
    asm volatile(
        "mma.sync.aligned.m16n8k8.row.col.f32.tf32.tf32.f32 "
        "{%0,%1,%2,%3}, {%4,%5,%6,%7}, {%8,%9}, {%10,%11,%12,%13};"
        : "=f"(d[0]), "=f"(d[1]), "=f"(d[2]), "=f"(d[3])
        : "r"(a[0]), "r"(a[1]), "r"(a[2]), "r"(a[3]), "r"(b0), "r"(b1),
          "f"(c[0]), "f"(c[1]), "f"(c[2]), "f"(c[3]));
}

// ---------------------------------------------------------------------------
// Kernel 1 (yn): y = x @ U via tensor cores, n = rowsum(y*y).
// CTA: 64 rows, 128 threads (4 warps x 16 rows). k-chunks of 64, double buf.
// ---------------------------------------------------------------------------
#define YXS(q) ((q) * 4352)             // [64][68] floats
#define YUS(q) (8704 + (q) * 2560)      // [64][40] floats
#define YN_SMEM ((8704 + 2 * 2560) * 4) // 55296 B

__global__ __launch_bounds__(128, 2) void yn_kernel(const float* __restrict__ x,
                                                    const float* __restrict__ U) {
    extern __shared__ float s[];
    const u32 su = s2u(s);

    const int tid  = threadIdx.x;
    const int w    = tid >> 5;
    const int lane = tid & 31;
    const int lq   = lane >> 2;
    const int lr   = lane & 3;
    const int row0 = blockIdx.x * 64;

    // prologue: chunk 0
    for (int idx = tid; idx < 1024; idx += 128) {
        int r_ = idx >> 4, u = idx & 15;
        cp16(su + (YXS(0) + r_ * 68 + u * 4) * 4,
             x + (size_t)(row0 + r_) * DD + u * 4);
    }
    for (int idx = tid; idx < 512; idx += 128) {
        int k = idx >> 3, u = idx & 7;
        cp16(su + (YUS(0) + k * 40 + u * 4) * 4, U + (size_t)k * RR + u * 4);
    }
    asm volatile("cp.async.commit_group;" ::: "memory");

    float acc[4][4];
#pragma unroll
    for (int nt = 0; nt < 4; nt++)
#pragma unroll
        for (int c = 0; c < 4; c++) acc[nt][c] = 0.f;

    for (int c = 0; c < 16; c++) {
        const int q = c & 1;
        asm volatile("cp.async.wait_group 0;" ::: "memory");
        __syncthreads();

        if (c + 1 < 16) {
            const int k0 = (c + 1) * 64;
            for (int idx = tid; idx < 1024; idx += 128) {
                int r_ = idx >> 4, u = idx & 15;
                cp16(su + (YXS(1 - q) + r_ * 68 + u * 4) * 4,
                     x + (size_t)(row0 + r_) * DD + k0 + u * 4);
            }
            for (int idx = tid; idx < 512; idx += 128) {
                int k = idx >> 3, u = idx & 7;
                cp16(su + (YUS(1 - q) + k * 40 + u * 4) * 4,
                     U + (size_t)(k0 + k) * RR + u * 4);
            }
            asm volatile("cp.async.commit_group;" ::: "memory");
        }

        const float* sX = s + YXS(q);
        const float* sU = s + YUS(q);
#pragma unroll
        for (int kt = 0; kt < 8; kt++) {
            u32 a[4];
            const int ab = (w * 16 + lq) * 68 + kt * 8 + lr;
            a[0] = fu(sX[ab]);
            a[1] = fu(sX[ab + 8 * 68]);
            a[2] = fu(sX[ab + 4]);
            a[3] = fu(sX[ab + 8 * 68 + 4]);
#pragma unroll
            for (int nt = 0; nt < 4; nt++) {
                u32 b0 = fu(sU[(kt * 8 + lr) * 40 + nt * 8 + lq]);
                u32 b1 = fu(sU[(kt * 8 + lr + 4) * 40 + nt * 8 + lq]);
                mma8(acc[nt], a, b0, b1, acc[nt]);
            }
        }
    }

    // epilogue: round, store y, compute n by quad reduction
    const int r0g = row0 + w * 16 + lq;
    const int r1g = r0g + 8;
    float n0 = 0.f, n1 = 0.f;
#pragma unroll
    for (int nt = 0; nt < 4; nt++) {
        float p0 = tf32f(acc[nt][0]), p1 = tf32f(acc[nt][1]);
        float p2 = tf32f(acc[nt][2]), p3 = tf32f(acc[nt][3]);
        *(float2*)&g_y[(size_t)r0g * RR + nt * 8 + lr * 2] = make_float2(p0, p1);
        *(float2*)&g_y[(size_t)r1g * RR + nt * 8 + lr * 2] = make_float2(p2, p3);
        n0 += p0 * p0 + p1 * p1;
        n1 += p2 * p2 + p3 * p3;
    }
    n0 += __shfl_xor_sync(0xffffffffu, n0, 1);
    n0 += __shfl_xor_sync(0xffffffffu, n0, 2);
    n1 += __shfl_xor_sync(0xffffffffu, n1, 1);
    n1 += __shfl_xor_sync(0xffffffffu, n1, 2);
    if (lr == 0) {
        g_n[r0g] = n0;
        g_n[r1g] = n1;
    }
}

// ---------------------------------------------------------------------------
// Kernel 2 (pk): P̂ = exp(2 Yi.Yj^T - ni - nj) + row partials + flags.
// CTA 128i x 128j; 8 warps = 4 wm x 2 wn. Stores ONLY flagged 64x32 tiles.
// ---------------------------------------------------------------------------
#define PK_YI 0        // [128][36]
#define PK_YJ 4608     // [128][36]
#define PK_NJ 9216     // [128]
#define PK_FL 9344     // 8 ints
#define PK_SL 9352     // [2][128]
#define PK_SMEM ((9352 + 256) * 4)
#define YSTR 36

__global__ __launch_bounds__(256, 2) void pk_kernel() {
    extern __shared__ float s[];
    const u32 su = s2u(s);
    int* sflag = (int*)s + PK_FL;

    const int tid  = threadIdx.x;
    const int w    = tid >> 5;
    const int lane = tid & 31;
    const int wm   = w >> 1;        // 0..3
    const int wn   = w & 1;         // 0..1
    const int lq   = lane >> 2;
    const int lr   = lane & 3;

    const int b   = blockIdx.z;
    const int i0  = blockIdx.y * 128;
    const int j0  = blockIdx.x * 128;
    const int bTT = b * TT;

    for (int idx = tid; idx < 1024; idx += 256) {
        int r_ = idx >> 3, u = idx & 7;
        cp16(su + (PK_YI + r_ * YSTR) * 4 + u * 16,
             g_y + (size_t)(bTT + i0 + r_) * RR + u * 4);
        cp16(su + (PK_YJ + r_ * YSTR) * 4 + u * 16,
             g_y + (size_t)(bTT + j0 + r_) * RR + u * 4);
    }
    if (tid < 32) cp16(su + PK_NJ * 4 + tid * 16, g_n + bTT + j0 + tid * 4);
    if (tid < 8) sflag[tid] = 0;
    asm volatile("cp.async.commit_group;" ::: "memory");
    asm volatile("cp.async.wait_group 0;" ::: "memory");
    __syncthreads();

    float ni[2][2];
#pragma unroll
    for (int mt = 0; mt < 2; mt++) {
        ni[mt][0] = g_n[bTT + i0 + wm * 32 + mt * 16 + lq];
        ni[mt][1] = g_n[bTT + i0 + wm * 32 + mt * 16 + lq + 8];
    }

    float S[2][8][4];
#pragma unroll
    for (int mt = 0; mt < 2; mt++)
#pragma unroll
        for (int nt = 0; nt < 8; nt++)
#pragma unroll
            for (int c = 0; c < 4; c++) S[mt][nt][c] = 0.f;

#pragma unroll
    for (int kt = 0; kt < 4; kt++) {
        u32 aY[2][4];
#pragma unroll
        for (int mt = 0; mt < 2; mt++) {
            const int yib = PK_YI + (wm * 32 + mt * 16 + lq) * YSTR + kt * 8 + lr;
            aY[mt][0] = fu(s[yib]);
            aY[mt][1] = fu(s[yib + 8 * YSTR]);
            aY[mt][2] = fu(s[yib + 4]);
            aY[mt][3] = fu(s[yib + 8 * YSTR + 4]);
        }
#pragma unroll
        for (int nt = 0; nt < 8; nt++) {
            const int yjb = PK_YJ + (wn * 64 + nt * 8 + lq) * YSTR + kt * 8 + lr;
            u32 b0 = fu(s[yjb]);
            u32 b1 = fu(s[yjb + 4]);
            mma8(S[0][nt], aY[0], b0, b1, S[0][nt]);
            mma8(S[1][nt], aY[1], b0, b1, S[1][nt]);
        }
    }

    // ---- arg = 2S - ni - nj (in place) ----
#pragma unroll
    for (int mt = 0; mt < 2; mt++) {
#pragma unroll
        for (int nt = 0; nt < 8; nt++) {
            const float2 nj = *(const float2*)&s[PK_NJ + wn * 64 + nt * 8 + lr * 2];
            S[mt][nt][0] = fmaf(S[mt][nt][0], 2.f, -ni[mt][0] - nj.x);
            S[mt][nt][1] = fmaf(S[mt][nt][1], 2.f, -ni[mt][0] - nj.y);
            S[mt][nt][2] = fmaf(S[mt][nt][2], 2.f, -ni[mt][1] - nj.x);
            S[mt][nt][3] = fmaf(S[mt][nt][3], 2.f, -ni[mt][1] - nj.y);
        }
    }

    // ---- per (mt, 32-col group) exact max -> activity + tile flags ----
    bool act[2][2];
#pragma unroll
    for (int mt = 0; mt < 2; mt++) {
#pragma unroll
        for (int G = 0; G < 2; G++) {
            float m_ = -1e30f;
#pragma unroll
            for (int nt = G * 4; nt < G * 4 + 4; nt++)
#pragma unroll
                for (int c = 0; c < 4; c++) m_ = fmaxf(m_, S[mt][nt][c]);
#pragma unroll
            for (int off = 16; off; off >>= 1)
                m_ = fmaxf(m_, __shfl_xor_sync(0xffffffffu, m_, off));
            act[mt][G] = (m_ > -25.0f);
            if (act[mt][G] && lane == 0)
                sflag[(wm >> 1) * 4 + wn * 2 + G] = 1;
        }
    }
    __syncthreads();   // sflag complete (OR across warps)

    // ---- exp + store ONLY for flagged 64x32 tiles ----
    float lsum[2][2] = {{0.f, 0.f}, {0.f, 0.f}};
#pragma unroll
    for (int mt = 0; mt < 2; mt++) {
#pragma unroll
        for (int G = 0; G < 2; G++) {
            if (sflag[(wm >> 1) * 4 + wn * 2 + G]) {
                if (act[mt][G]) {
#pragma unroll
                    for (int nt = G * 4; nt < G * 4 + 4; nt++) {
                        float p0 = tf32f(__expf(S[mt][nt][0]));
                        float p1 = tf32f(__expf(S[mt][nt][1]));
                        float p2 = tf32f(__expf(S[mt][nt][2]));
                        float p3 = tf32f(__expf(S[mt][nt][3]));
                        lsum[mt][0] += p0 + p1;
                        lsum[mt][1] += p2 + p3;
                        const size_t r0 = (size_t)(bTT + i0 + wm * 32 + mt * 16 + lq) * TT
                                          + j0 + wn * 64 + nt * 8 + lr * 2;
                        *(float2*)&g_p[r0]          = make_float2(p0, p1);
                        *(float2*)&g_p[r0 + 8 * TT] = make_float2(p2, p3);
                    }
                } else {
#pragma unroll
                    for (int nt = G * 4; nt < G * 4 + 4; nt++) {
                        const size_t r0 = (size_t)(bTT + i0 + wm * 32 + mt * 16 + lq) * TT
                                          + j0 + wn * 64 + nt * 8 + lr * 2;
                        *(float2*)&g_p[r0]          = make_float2(0.f, 0.f);
                        *(float2*)&g_p[r0 + 8 * TT] = make_float2(0.f, 0.f);
                    }
                }
            }
        }
    }

    // ---- row partials + flags out ----
#pragma unroll
    for (int mt = 0; mt < 2; mt++)
#pragma unroll
        for (int h = 0; h < 2; h++) {
            float v = lsum[mt][h];
            v += __shfl_xor_sync(0xffffffffu, v, 1);
            v += __shfl_xor_sync(0xffffffffu, v, 2);
            if (lr == 0)
                s[PK_SL + wn * 128 + wm * 32 + mt * 16 + lq + 8 * h] = v;
        }
    __syncthreads();
    if (tid < 128) {
        g_lp[(size_t)(bTT + i0 + tid) * 16 + blockIdx.x] =
            s[PK_SL + tid] + s[PK_SL + 128 + tid];
    }
    if (tid < 8) {
        const int mtile = (i0 >> 6) + (tid >> 2);
        const int kt    = (j0 >> 5) + (tid & 3);
        g_flag[(b * 32 + mtile) * 64 + kt] = sflag[tid];
    }
}

// ---------------------------------------------------------------------------
// Kernel 3 (gemm2): out = (P̂ @ rna(x)) / l, visiting only flagged k-tiles.
// CTA = 64m x 256n; 8 warps = 2 wm x 4 wn; warp 32m x 64n; 2 CTAs/SM.
// ---------------------------------------------------------------------------
#define A_F(q) ((q) * 2304)             // [64][36] x2
#define X_F(q) (4608 + (q) * 8448)      // [32][264] x2
#define G2_SMEM ((4608 + 2 * 8448) * 4) // 86016 B
#define XSTR 264

#define G2_LOAD(tt, qq) do {                                                   \
    for (int idx = tid; idx < 512; idx += 256) {                               \
        int r_ = idx >> 3, u = idx & 7;                                        \
        cp16(su + A_F(qq) * 4 + (r_ * YSTR + u * 4) * 4,                       \
             g_p + (size_t)(bTT + m0 + r_) * TT + (tt) * 32 + u * 4);          \
    }                                                                          \
    for (int idx = tid; idx < 2048; idx += 256) {                              \
        int r_ = idx >> 6, u = idx & 63;                                       \
        cp16(su + X_F(qq) * 4 + (r_ * XSTR + u * 4) * 4,                       \
             x + (size_t)(bTT + (tt) * 32 + r_) * DD + dc0 + u * 4);           \
    }                                                                          \
    asm volatile("cp.async.commit_group;" ::: "memory");                       \
} while (0)

__global__ __launch_bounds__(256, 2) void gemm2_kernel(const float* __restrict__ x,
                                                       float* __restrict__ out) {
    extern __shared__ float s[];
    const u32 su = s2u(s);

    const int tid  = threadIdx.x;
    const int w    = tid >> 5;
    const int lane = tid & 31;
    const int wm   = w >> 2;        // 0..1
    const int wn   = w & 3;         // 0..3
    const int lq   = lane >> 2;
    const int lr   = lane & 3;

    const int b   = blockIdx.z;
    const int m0  = blockIdx.y * 64;
    const int dc0 = blockIdx.x * 256;
    const int bTT = b * TT;

    const int* fb = &g_flag[(b * 32 + (m0 >> 6)) * 64];

    float acc[2][8][4];
#pragma unroll
    for (int mt = 0; mt < 2; mt++)
#pragma unroll
        for (int nt = 0; nt < 8; nt++)
#pragma unroll
            for (int c = 0; c < 4; c++) acc[mt][nt][c] = 0.f;

    int t = 0;
    while (t < 64 && fb[t] == 0) t++;
    int q = 0;
    if (t < 64) G2_LOAD(t, 0);

    while (t < 64) {
        int tn = t + 1;
        while (tn < 64 && fb[tn] == 0) tn++;

        asm volatile("cp.async.wait_group 0;" ::: "memory");
        __syncthreads();

        if (tn < 64) G2_LOAD(tn, 1 - q);

        // A fragments (P rows)
        u32 aP[2][4][4];
#pragma unroll
        for (int mt = 0; mt < 2; mt++) {
            const int pab = A_F(q) + (wm * 32 + mt * 16 + lq) * YSTR + lr;
#pragma unroll
            for (int kt = 0; kt < 4; kt++) {
                aP[mt][kt][0] = fu(s[pab + kt * 8]);
                aP[mt][kt][1] = fu(s[pab + kt * 8 + 8 * YSTR]);
                aP[mt][kt][2] = fu(s[pab + kt * 8 + 4]);
                aP[mt][kt][3] = fu(s[pab + kt * 8 + 8 * YSTR + 4]);
            }
        }
        const int xb = X_F(q) + lr * XSTR + wn * 64 + lq;
#pragma unroll
        for (int nt = 0; nt < 8; nt++) {
#pragma unroll
            for (int kt = 0; kt < 4; kt++) {
                u32 b0 = tf32u(s[xb + kt * 8 * XSTR + nt * 8]);
                u32 b1 = tf32u(s[xb + (kt * 8 + 4) * XSTR + nt * 8]);
                mma8(acc[0][nt], aP[0][kt], b0, b1, acc[0][nt]);
                mma8(acc[1][nt], aP[1][kt], b0, b1, acc[1][nt]);
            }
        }

        q ^= 1;
        t = tn;
    }

    // ---- epilogue: normalize by l = sum of 16 partials, store ----
#pragma unroll
    for (int mt = 0; mt < 2; mt++) {
#pragma unroll
        for (int h = 0; h < 2; h++) {
            const int row = wm * 32 + mt * 16 + lq + 8 * h;
            const float* lp = &g_lp[(size_t)(bTT + m0 + row) * 16];
            const float4 a0 = *(const float4*)(lp + 0);
            const float4 a1 = *(const float4*)(lp + 4);
            const float4 a2 = *(const float4*)(lp + 8);
            const float4 a3 = *(const float4*)(lp + 12);
            const float l = ((a0.x + a0.y) + (a0.z + a0.w)) +
                            ((a1.x + a1.y) + (a1.z + a1.w)) +
                            ((a2.x + a2.y) + (a2.z + a2.w)) +
                            ((a3.x + a3.y) + (a3.z + a3.w));
            const float inv = 1.0f / l;
            float* o = out + (size_t)(bTT + m0 + row) * DD + dc0 + wn * 64 + lr * 2;
#pragma unroll
            for (int nt = 0; nt < 8; nt++) {
                *(float2*)(o + nt * 8) = make_float2(acc[mt][nt][2 * h] * inv,
                                                     acc[mt][nt][2 * h + 1] * inv);
            }
        }
    }
}

extern "C" void kernel_launch(void* const* d_in, const int* in_sizes, int n_in,
                              void* d_out, int out_size) {
    const float* x = (const float*)d_in[0];   // [B,T,D] fp32
    const float* U = (const float*)d_in[1];   // [D,R]   fp32
    float* out = (float*)d_out;

    cudaFuncSetAttribute(yn_kernel, cudaFuncAttributeMaxDynamicSharedMemorySize,
                         YN_SMEM);
    yn_kernel<<<(BB * TT) / 64, 128, YN_SMEM>>>(x, U);

    dim3 gpk(TT / 128, TT / 128, BB);
    pk_kernel<<<gpk, 256, PK_SMEM>>>();

    cudaFuncSetAttribute(gemm2_kernel, cudaFuncAttributeMaxDynamicSharedMemorySize,
                         G2_SMEM);
    dim3 g2(DD / 256, TT / 64, BB);
    gemm2_kernel<<<g2, 256, G2_SMEM>>>(x, out);
}